// round 15
// baseline (speedup 1.0000x reference)
#include <cuda_runtime.h>
#include <cstdint>
#include <math.h>

// RoIAlign_withBanks: N=2000 boxes, C=256, G=7, 6 FPN levels, dims {38,19,10,5,3,1}.
// Output [N, C, 7, 7] fp32.
//
// R15 = R14 with register trim for occupancy: single-float4 prefetch (covers
// P<=12, the common case; larger P uses the direct-gather tail) and
// __launch_bounds__(196,7). Same transpose + dedup-gather + double-buffered
// 64-ch chunk pipeline, register-prefetch LDG gather (L1-cached; cp.async
// proven to bypass L1 on sm_100a).

#define G_POOL 7
#define CELLS  49
#define NCH    256
#define TPB    196
#define PCAP   48          // max unique patch points (math bound 42)
#define CPAD   68          // padded floats per point per 64-ch chunk (17 float4)
#define NPOS   1940        // 1444+361+100+25+9+1

__device__ __align__(16) float g_ftrans[NPOS * NCH];   // [pos][channel]

// ---------------- transpose: fm[c][p] -> g_ftrans[p][c], coalesced both ways
__global__ __launch_bounds__(256) void transpose_fmaps_kernel(
    const float* __restrict__ f0, const float* __restrict__ f1,
    const float* __restrict__ f2, const float* __restrict__ f3,
    const float* __restrict__ f4, const float* __restrict__ f5)
{
    __shared__ float sT[32][NCH + 1];
    const int b = blockIdx.x;
    const float* fm; int DD, p0, gb;
    if      (b < 46) { fm = f0; DD = 1444; p0 = b * 32;        gb = 0; }
    else if (b < 58) { fm = f1; DD = 361;  p0 = (b - 46) * 32; gb = 1444; }
    else if (b < 62) { fm = f2; DD = 100;  p0 = (b - 58) * 32; gb = 1805; }
    else if (b == 62){ fm = f3; DD = 25;   p0 = 0;             gb = 1905; }
    else if (b == 63){ fm = f4; DD = 9;    p0 = 0;             gb = 1930; }
    else             { fm = f5; DD = 1;    p0 = 0;             gb = 1939; }
    const int np = min(32, DD - p0);

    const int x = threadIdx.x & 31;       // position within tile
    const int y = threadIdx.x >> 5;       // warp id (0..7)
    if (x < np) {
#pragma unroll
        for (int cc = 0; cc < 32; ++cc) {
            int c = cc * 8 + y;           // coalesced read along p for fixed c
            sT[x][c] = fm[c * DD + p0 + x];
        }
    }
    __syncthreads();
    for (int px = 0; px < np; ++px)
        g_ftrans[(gb + p0 + px) * NCH + threadIdx.x] = sT[px][threadIdx.x];
}

__device__ __forceinline__ int nth_set_bit(unsigned long long m, int n) {
    for (int k = 0; k < n; ++k) m &= m - 1;
    return __ffsll(m) - 1;
}

__global__ __launch_bounds__(TPB, 7) void roialign_banks_kernel(
    const float* __restrict__ boxes,
    float* __restrict__ out)
{
    __shared__ __align__(16) float s_patch[2][PCAP * CPAD];   // 2 x 13056 B
    __shared__ int   s_gidx[PCAP];
    __shared__ int   s_ix0[G_POOL], s_ix1[G_POOL], s_iy0[G_POOL], s_iy1[G_POOL];
    __shared__ float s_px0[G_POOL], s_py0[G_POOL];

    const int n = blockIdx.x;
    const int t = threadIdx.x;

    const float bx1 = boxes[4 * n + 0];
    const float by1 = boxes[4 * n + 1];
    const float bx2 = boxes[4 * n + 2];
    const float by2 = boxes[4 * n + 3];

    // Level: clip(floor(5 + log2(sqrt(w*h))), 0, 5)
    const float avg = sqrtf((bx2 - bx1) * (by2 - by1));
    const float lf  = floorf(5.0f + log2f(avg));
    const int lvl   = (int)fminf(fmaxf(lf, 0.0f), 5.0f);

    int D, gbase;
    switch (lvl) {
        case 0:  D = 38; gbase = 0;    break;
        case 1:  D = 19; gbase = 1444; break;
        case 2:  D = 10; gbase = 1805; break;
        case 3:  D = 5;  gbase = 1905; break;
        case 4:  D = 3;  gbase = 1930; break;
        default: D = 1;  gbase = 1939; break;
    }

    // --- per-axis grid coords (two warps in parallel) ---
    if (t < G_POOL) {
        float xr = fminf(fmaxf(bx1 + (float)t * (bx2 - bx1) / 6.0f, 0.0f), 1.0f);
        float ux = xr * (float)(D - 1);
        float fx = floorf(ux);
        s_ix0[t] = (int)fx;
        s_ix1[t] = (int)ceilf(ux);
        s_px0[t] = 1.0f - (ux - fx);      // ceil-floor in {0,1} -> dd = 1
    } else if (t >= 32 && t < 32 + G_POOL) {
        int j = t - 32;
        float yr = fminf(fmaxf(by1 + (float)j * (by2 - by1) / 6.0f, 0.0f), 1.0f);
        float uy = yr * (float)(D - 1);
        float fy = floorf(uy);
        s_iy0[j] = (int)fy;
        s_iy1[j] = (int)ceilf(uy);
        s_py0[j] = 1.0f - (uy - fy);
    }
    __syncthreads();

    // --- unique-coord masks: redundant per-thread (broadcast LDS) ---
    unsigned long long mx = 0ull, my = 0ull;
#pragma unroll
    for (int i = 0; i < G_POOL; ++i) {
        mx |= (1ull << s_ix0[i]) | (1ull << s_ix1[i]);
        my |= (1ull << s_iy0[i]) | (1ull << s_iy1[i]);
    }
    const int UYn = __popcll(my);
    const int P   = __popcll(mx) * UYn;

    // --- gather index table: patch slot (u,v) -> plane offset X[u]*D + Y[v]
    if (t < P) {
        int u = t / UYn, v = t - u * UYn;
        s_gidx[t] = nth_set_bit(mx, u) * D + nth_set_bit(my, v);
    }

    // --- per-thread cell meta (registers) ---
    const int c0  = t / CELLS;            // 0..3
    const int pos = t - c0 * CELLS;
    const int i   = pos / G_POOL;
    const int j   = pos - i * G_POOL;
    const int ix0 = s_ix0[i], ix1 = s_ix1[i];
    const int iy0 = s_iy0[j], iy1 = s_iy1[j];
    const float px0 = s_px0[i], py0 = s_py0[j];
    const int a0 = __popcll(mx & ((1ull << ix0) - 1ull));
    const int a1 = __popcll(mx & ((1ull << ix1) - 1ull));
    const int b0 = __popcll(my & ((1ull << iy0) - 1ull));
    const int b1 = __popcll(my & ((1ull << iy1) - 1ull));
    const int o00 = a0 * UYn + b0, o10 = a1 * UYn + b0;
    const int o01 = a0 * UYn + b1, o11 = a1 * UYn + b1;
    const float px1 = 1.0f - px0, py1 = 1.0f - py0;
    const float w00 = px0 * py0, w10 = px1 * py0;
    const float w01 = px0 * py1, w11 = px1 * py1;

    __syncthreads();   // s_gidx ready

    const float4* gt  = (const float4*)g_ftrans + (size_t)gbase * (NCH / 4);
    const int     nt4 = (NCH / 4 / 4) * P;        // 16 float4 per point per chunk
    float* const  outn = out + (size_t)n * (NCH * CELLS) + 147 * c0 + t;

    // ---- initial gather: chunk 0 into buffer 0 ----
    {
        float4* db = (float4*)s_patch[0];
        for (int idx = t; idx < nt4; idx += TPB) {
            int pp = idx >> 4, cc = idx & 15;
            db[pp * (CPAD / 4) + cc] = gt[s_gidx[pp] * (NCH / 4) + cc];
        }
    }
    __syncthreads();

#pragma unroll
    for (int k = 0; k < 4; ++k) {
        // ---- prefetch first TPB words of chunk k+1 into one register float4
        float4 pf0;
        bool h0 = false;
        if (k < 3 && t < nt4) {
            const float4* gs = gt + (k + 1) * 16;
            pf0 = gs[s_gidx[t >> 4] * (NCH / 4) + (t & 15)];
            h0 = true;
        }

        // ---- sample chunk k from buffer k&1 ----
        {
            const float* buf = s_patch[k & 1];
            const float4* q00 = (const float4*)(buf + o00 * CPAD);
            const float4* q10 = (const float4*)(buf + o10 * CPAD);
            const float4* q01 = (const float4*)(buf + o01 * CPAD);
            const float4* q11 = (const float4*)(buf + o11 * CPAD);
            float* op = outn + k * 64 * CELLS;
#pragma unroll
            for (int e = 0; e < 4; ++e) {
                const int fi = c0 + 4 * e;       // channels 4*fi..+3 of chunk
                float4 v00 = q00[fi];
                float4 v10 = q10[fi];
                float4 v01 = q01[fi];
                float4 v11 = q11[fi];
                float r0 = w00 * v00.x + w10 * v10.x + w01 * v01.x + w11 * v11.x;
                float r1 = w00 * v00.y + w10 * v10.y + w01 * v01.y + w11 * v11.y;
                float r2 = w00 * v00.z + w10 * v10.z + w01 * v01.z + w11 * v11.z;
                float r3 = w00 * v00.w + w10 * v10.w + w01 * v01.w + w11 * v11.w;
                op[0]         = r0;
                op[CELLS]     = r1;
                op[2 * CELLS] = r2;
                op[3 * CELLS] = r3;
                op += 16 * CELLS;                // next 16 channels
            }
        }

        // ---- commit prefetched chunk k+1 into the other buffer ----
        if (k < 3) {
            float4* db = (float4*)s_patch[(k + 1) & 1];
            if (h0) db[(t >> 4) * (CPAD / 4) + (t & 15)] = pf0;
            // tail (P > 12): direct gather, not overlapped (rare boxes)
            const float4* gs = gt + (k + 1) * 16;
            for (int idx = t + TPB; idx < nt4; idx += TPB)
                db[(idx >> 4) * (CPAD / 4) + (idx & 15)] =
                    gs[s_gidx[idx >> 4] * (NCH / 4) + (idx & 15)];
            __syncthreads();
        }
    }
}

extern "C" void kernel_launch(void* const* d_in, const int* in_sizes, int n_in,
                              void* d_out, int out_size)
{
    const int N = in_sizes[0] / 4;
    transpose_fmaps_kernel<<<65, 256>>>(
        (const float*)d_in[1], (const float*)d_in[2], (const float*)d_in[3],
        (const float*)d_in[4], (const float*)d_in[5], (const float*)d_in[6]);
    roialign_banks_kernel<<<N, TPB>>>(
        (const float*)d_in[0], (float*)d_out);
}

// round 16
// speedup vs baseline: 1.1800x; 1.1800x over previous
#include <cuda_runtime.h>
#include <cstdint>
#include <math.h>

// RoIAlign_withBanks: N=2000 boxes, C=256, G=7, 6 FPN levels, dims {38,19,10,5,3,1}.
// Output [N, C, 7, 7] fp32.
//
// R16 = R14 (proven 31.1us main kernel: transpose + dedup-gather + register-
// prefetch double-buffered 64-ch chunks at 6 blocks/SM — occupancy MUST stay
// at 6: more resident blocks eat the L1 carveout and push gathers to L2) with:
//  - transpose at 2x parallelism (125 blocks x 16-position tiles)
//  - s_gidx values hoisted to registers (kills LDS->LDG serial chain in gather)
//  - __launch_bounds__(196,6) pins the 6-block residency (reg cap 55).

#define G_POOL 7
#define CELLS  49
#define NCH    256
#define TPB    196
#define PCAP   48          // max unique patch points (math bound 42)
#define CPAD   68          // padded floats per point per 64-ch chunk (17 float4)
#define NPOS   1940        // 1444+361+100+25+9+1

__device__ __align__(16) float g_ftrans[NPOS * NCH];   // [pos][channel]

// ---------------- transpose: fm[c][p] -> g_ftrans[p][c]
// 125 blocks x 16-position tiles; reads half-warp coalesced, writes fully
// coalesced (256 threads across the channel row).
__global__ __launch_bounds__(256) void transpose_fmaps_kernel(
    const float* __restrict__ f0, const float* __restrict__ f1,
    const float* __restrict__ f2, const float* __restrict__ f3,
    const float* __restrict__ f4, const float* __restrict__ f5)
{
    __shared__ float sT[16][NCH + 1];
    const int b = blockIdx.x;
    const float* fm; int DD, p0, gb;
    if      (b < 91)  { fm = f0; DD = 1444; p0 = b * 16;         gb = 0; }
    else if (b < 114) { fm = f1; DD = 361;  p0 = (b - 91) * 16;  gb = 1444; }
    else if (b < 121) { fm = f2; DD = 100;  p0 = (b - 114) * 16; gb = 1805; }
    else if (b < 123) { fm = f3; DD = 25;   p0 = (b - 121) * 16; gb = 1905; }
    else if (b == 123){ fm = f4; DD = 9;    p0 = 0;              gb = 1930; }
    else              { fm = f5; DD = 1;    p0 = 0;              gb = 1939; }
    const int np = min(16, DD - p0);

    const int x = threadIdx.x & 15;        // position within tile
    const int cbase = threadIdx.x >> 4;    // 0..15
    if (x < np) {
#pragma unroll
        for (int pass = 0; pass < 16; ++pass) {
            int c = pass * 16 + cbase;
            sT[x][c] = fm[c * DD + p0 + x];
        }
    }
    __syncthreads();
    for (int px = 0; px < np; ++px)
        g_ftrans[(gb + p0 + px) * NCH + threadIdx.x] = sT[px][threadIdx.x];
}

__device__ __forceinline__ int nth_set_bit(unsigned long long m, int n) {
    for (int k = 0; k < n; ++k) m &= m - 1;
    return __ffsll(m) - 1;
}

__global__ __launch_bounds__(TPB, 6) void roialign_banks_kernel(
    const float* __restrict__ boxes,
    float* __restrict__ out)
{
    __shared__ __align__(16) float s_patch[2][PCAP * CPAD];   // 2 x 13056 B
    __shared__ int   s_gidx[PCAP];
    __shared__ int   s_ix0[G_POOL], s_ix1[G_POOL], s_iy0[G_POOL], s_iy1[G_POOL];
    __shared__ float s_px0[G_POOL], s_py0[G_POOL];

    const int n = blockIdx.x;
    const int t = threadIdx.x;

    const float bx1 = boxes[4 * n + 0];
    const float by1 = boxes[4 * n + 1];
    const float bx2 = boxes[4 * n + 2];
    const float by2 = boxes[4 * n + 3];

    // Level: clip(floor(5 + log2(sqrt(w*h))), 0, 5)
    const float avg = sqrtf((bx2 - bx1) * (by2 - by1));
    const float lf  = floorf(5.0f + log2f(avg));
    const int lvl   = (int)fminf(fmaxf(lf, 0.0f), 5.0f);

    int D, gbase;
    switch (lvl) {
        case 0:  D = 38; gbase = 0;    break;
        case 1:  D = 19; gbase = 1444; break;
        case 2:  D = 10; gbase = 1805; break;
        case 3:  D = 5;  gbase = 1905; break;
        case 4:  D = 3;  gbase = 1930; break;
        default: D = 1;  gbase = 1939; break;
    }

    // --- per-axis grid coords (two warps in parallel) ---
    if (t < G_POOL) {
        float xr = fminf(fmaxf(bx1 + (float)t * (bx2 - bx1) / 6.0f, 0.0f), 1.0f);
        float ux = xr * (float)(D - 1);
        float fx = floorf(ux);
        s_ix0[t] = (int)fx;
        s_ix1[t] = (int)ceilf(ux);
        s_px0[t] = 1.0f - (ux - fx);      // ceil-floor in {0,1} -> dd = 1
    } else if (t >= 32 && t < 32 + G_POOL) {
        int j = t - 32;
        float yr = fminf(fmaxf(by1 + (float)j * (by2 - by1) / 6.0f, 0.0f), 1.0f);
        float uy = yr * (float)(D - 1);
        float fy = floorf(uy);
        s_iy0[j] = (int)fy;
        s_iy1[j] = (int)ceilf(uy);
        s_py0[j] = 1.0f - (uy - fy);
    }
    __syncthreads();

    // --- unique-coord masks: redundant per-thread (broadcast LDS) ---
    unsigned long long mx = 0ull, my = 0ull;
#pragma unroll
    for (int i = 0; i < G_POOL; ++i) {
        mx |= (1ull << s_ix0[i]) | (1ull << s_ix1[i]);
        my |= (1ull << s_iy0[i]) | (1ull << s_iy1[i]);
    }
    const int UYn = __popcll(my);
    const int P   = __popcll(mx) * UYn;

    // --- gather index table: patch slot (u,v) -> plane offset X[u]*D + Y[v]
    if (t < P) {
        int u = t / UYn, v = t - u * UYn;
        s_gidx[t] = nth_set_bit(mx, u) * D + nth_set_bit(my, v);
    }

    // --- per-thread cell meta (registers) ---
    const int c0  = t / CELLS;            // 0..3
    const int pos = t - c0 * CELLS;
    const int i   = pos / G_POOL;
    const int j   = pos - i * G_POOL;
    const int ix0 = s_ix0[i], ix1 = s_ix1[i];
    const int iy0 = s_iy0[j], iy1 = s_iy1[j];
    const float px0 = s_px0[i], py0 = s_py0[j];
    const int a0 = __popcll(mx & ((1ull << ix0) - 1ull));
    const int a1 = __popcll(mx & ((1ull << ix1) - 1ull));
    const int b0 = __popcll(my & ((1ull << iy0) - 1ull));
    const int b1 = __popcll(my & ((1ull << iy1) - 1ull));
    const int o00 = a0 * UYn + b0, o10 = a1 * UYn + b0;
    const int o01 = a0 * UYn + b1, o11 = a1 * UYn + b1;
    const float px1 = 1.0f - px0, py1 = 1.0f - py0;
    const float w00 = px0 * py0, w10 = px1 * py0;
    const float w01 = px0 * py1, w11 = px1 * py1;

    __syncthreads();   // s_gidx ready

    const float4* gt  = (const float4*)g_ftrans + (size_t)gbase * (NCH / 4);
    const int     nt4 = (NCH / 4 / 4) * P;        // 16 float4 per point per chunk
    float* const  outn = out + (size_t)n * (NCH * CELLS) + 147 * c0 + t;

    // ---- hoist the <=4 gather indices this thread ever needs into registers
    // (kills the serial LDS->LDG chain inside the gather/prefetch loops)
    const int gp0 = min(t >> 4, PCAP - 1);
    const int gp1 = min((t + TPB) >> 4, PCAP - 1);
    const int gp2 = min((t + 2 * TPB) >> 4, PCAP - 1);
    const int gp3 = min((t + 3 * TPB) >> 4, PCAP - 1);
    const int g0 = s_gidx[gp0] * (NCH / 4);
    const int g1 = s_gidx[gp1] * (NCH / 4);
    const int g2 = s_gidx[gp2] * (NCH / 4);
    const int g3 = s_gidx[gp3] * (NCH / 4);

    // ---- initial gather: chunk 0 into buffer 0 (explicit 4-step) ----
    {
        float4* db = (float4*)s_patch[0];
        int idx = t;
        if (idx < nt4) db[(idx >> 4) * (CPAD / 4) + (idx & 15)] = gt[g0 + (idx & 15)];
        idx += TPB;
        if (idx < nt4) db[(idx >> 4) * (CPAD / 4) + (idx & 15)] = gt[g1 + (idx & 15)];
        idx += TPB;
        if (idx < nt4) db[(idx >> 4) * (CPAD / 4) + (idx & 15)] = gt[g2 + (idx & 15)];
        idx += TPB;
        if (idx < nt4) db[(idx >> 4) * (CPAD / 4) + (idx & 15)] = gt[g3 + (idx & 15)];
    }
    __syncthreads();

#pragma unroll
    for (int k = 0; k < 4; ++k) {
        // ---- prefetch first TPB words of chunk k+1 into one register float4
        float4 pf0;
        bool h0 = false;
        if (k < 3 && t < nt4) {
            pf0 = gt[(k + 1) * 16 + g0 + (t & 15)];
            h0 = true;
        }

        // ---- sample chunk k from buffer k&1 ----
        {
            const float* buf = s_patch[k & 1];
            const float4* q00 = (const float4*)(buf + o00 * CPAD);
            const float4* q10 = (const float4*)(buf + o10 * CPAD);
            const float4* q01 = (const float4*)(buf + o01 * CPAD);
            const float4* q11 = (const float4*)(buf + o11 * CPAD);
            float* op = outn + k * 64 * CELLS;
#pragma unroll
            for (int e = 0; e < 4; ++e) {
                const int fi = c0 + 4 * e;       // channels 4*fi..+3 of chunk
                float4 v00 = q00[fi];
                float4 v10 = q10[fi];
                float4 v01 = q01[fi];
                float4 v11 = q11[fi];
                float r0 = w00 * v00.x + w10 * v10.x + w01 * v01.x + w11 * v11.x;
                float r1 = w00 * v00.y + w10 * v10.y + w01 * v01.y + w11 * v11.y;
                float r2 = w00 * v00.z + w10 * v10.z + w01 * v01.z + w11 * v11.z;
                float r3 = w00 * v00.w + w10 * v10.w + w01 * v01.w + w11 * v11.w;
                op[0]         = r0;
                op[CELLS]     = r1;
                op[2 * CELLS] = r2;
                op[3 * CELLS] = r3;
                op += 16 * CELLS;                // next 16 channels
            }
        }

        // ---- commit prefetched chunk k+1 into the other buffer ----
        if (k < 3) {
            float4* db = (float4*)s_patch[(k + 1) & 1];
            if (h0) db[(t >> 4) * (CPAD / 4) + (t & 15)] = pf0;
            // tail (P > 12): register-indexed gather, not overlapped (rare)
            const float4* gs = gt + (k + 1) * 16;
            int idx = t + TPB;
            if (idx < nt4) db[(idx >> 4) * (CPAD / 4) + (idx & 15)] = gs[g1 + (idx & 15)];
            idx += TPB;
            if (idx < nt4) db[(idx >> 4) * (CPAD / 4) + (idx & 15)] = gs[g2 + (idx & 15)];
            idx += TPB;
            if (idx < nt4) db[(idx >> 4) * (CPAD / 4) + (idx & 15)] = gs[g3 + (idx & 15)];
            __syncthreads();
        }
    }
}

extern "C" void kernel_launch(void* const* d_in, const int* in_sizes, int n_in,
                              void* d_out, int out_size)
{
    const int N = in_sizes[0] / 4;
    transpose_fmaps_kernel<<<125, 256>>>(
        (const float*)d_in[1], (const float*)d_in[2], (const float*)d_in[3],
        (const float*)d_in[4], (const float*)d_in[5], (const float*)d_in[6]);
    roialign_banks_kernel<<<N, TPB>>>(
        (const float*)d_in[0], (float*)d_out);
}